// round 13
// baseline (speedup 1.0000x reference)
#include <cuda_runtime.h>
#include <math.h>
#include <stdint.h>

// ---- problem constants ----
#define BB    2
#define HIDN  2048
#define NHH   16
#define LLN   8
#define VV    32000
#define DDIM  128
#define OFFN  1024
#define RRES  1025
#define PHEAP 11272
#define NK    2049
#define FFN   8192
#define SSEQ  2048
#define NCHUNK 17

// ---- device scratch (allocation-free) ----
__device__ __align__(16) float g_x [BB][HIDN];
__device__ __align__(16) float g_q [BB][NHH][DDIM];
__device__ __align__(16) float g_kscr[LLN][BB][NHH][DDIM];
__device__ __align__(16) float g_vscr[LLN][BB][NHH][DDIM];
__device__ __align__(16) float g_h[BB][FFN];
__device__ float g_pm[NCHUNK][BB * NHH];
__device__ float g_ps[NCHUNK][BB * NHH];
__device__ __align__(16) float g_po[NCHUNK][BB * NHH][DDIM];
__device__ unsigned int g_cnt[BB * NHH];   // zero-init; self-resetting

// ============================================================
// x = x + sinusoidal PE(pos)
// ============================================================
__global__ void k_init(const float* __restrict__ x, const int* __restrict__ posp) {
    int b = blockIdx.x;
    float pos = (float)(*posp);
    for (int e = threadIdx.x; e < HIDN; e += blockDim.x) {
        int i = e >> 1;
        float div = expf(-logf(10000.0f) * (2.0f * (float)i) / (float)HIDN);
        float ang = pos * div;
        float pe = (e & 1) ? cosf(ang) : sinf(ang);
        g_x[b][e] = x[(size_t)b * HIDN + e] + pe;
    }
}

// ============================================================
// LN prologue (warp-shuffle, 3 barriers). block = 256 threads.
// xs layout: [0,512) = batch0 float4, [512,1024) = batch1 float4.
// ============================================================
__device__ __forceinline__ void stage_ln(float4* xs,
                                         const float* __restrict__ gam,
                                         const float* __restrict__ bet) {
    int tid = threadIdx.x, lane = tid & 31, warp = tid >> 5;
    __shared__ float4 wred[8];
    __shared__ float4 stats;   // mean0, rstd0, mean1, rstd1
    const float4* x0 = (const float4*)g_x[0];
    const float4* x1 = (const float4*)g_x[1];
    float4 a0 = x0[tid], a1 = x0[tid + 256];
    float4 b0 = x1[tid], b1 = x1[tid + 256];
    float s0 = a0.x + a0.y + a0.z + a0.w + a1.x + a1.y + a1.z + a1.w;
    float s1 = b0.x + b0.y + b0.z + b0.w + b1.x + b1.y + b1.z + b1.w;
    float q0 = a0.x*a0.x + a0.y*a0.y + a0.z*a0.z + a0.w*a0.w
             + a1.x*a1.x + a1.y*a1.y + a1.z*a1.z + a1.w*a1.w;
    float q1 = b0.x*b0.x + b0.y*b0.y + b0.z*b0.z + b0.w*b0.w
             + b1.x*b1.x + b1.y*b1.y + b1.z*b1.z + b1.w*b1.w;
    #pragma unroll
    for (int off = 16; off > 0; off >>= 1) {
        s0 += __shfl_down_sync(0xffffffffu, s0, off);
        q0 += __shfl_down_sync(0xffffffffu, q0, off);
        s1 += __shfl_down_sync(0xffffffffu, s1, off);
        q1 += __shfl_down_sync(0xffffffffu, q1, off);
    }
    if (lane == 0) wred[warp] = make_float4(s0, q0, s1, q1);
    __syncthreads();
    if (warp == 0) {
        float4 v = wred[lane & 7];
        float t0 = v.x, t1 = v.y, t2 = v.z, t3 = v.w;
        #pragma unroll
        for (int off = 4; off > 0; off >>= 1) {
            t0 += __shfl_down_sync(0xffffffffu, t0, off, 8);
            t1 += __shfl_down_sync(0xffffffffu, t1, off, 8);
            t2 += __shfl_down_sync(0xffffffffu, t2, off, 8);
            t3 += __shfl_down_sync(0xffffffffu, t3, off, 8);
        }
        if (lane == 0) {
            float mean0 = t0 * (1.0f / HIDN);
            float mean1 = t2 * (1.0f / HIDN);
            float var0  = t1 * (1.0f / HIDN) - mean0 * mean0;
            float var1  = t3 * (1.0f / HIDN) - mean1 * mean1;
            stats = make_float4(mean0, rsqrtf(var0 + 1e-5f),
                                mean1, rsqrtf(var1 + 1e-5f));
        }
    }
    __syncthreads();
    float4 st = stats;
    const float4* g4 = (const float4*)gam;
    const float4* e4 = (const float4*)bet;
    float4 ga = g4[tid], gb = g4[tid + 256];
    float4 ea = e4[tid], eb = e4[tid + 256];
    xs[tid] = make_float4((a0.x - st.x) * st.y * ga.x + ea.x,
                          (a0.y - st.x) * st.y * ga.y + ea.y,
                          (a0.z - st.x) * st.y * ga.z + ea.z,
                          (a0.w - st.x) * st.y * ga.w + ea.w);
    xs[tid + 256] = make_float4((a1.x - st.x) * st.y * gb.x + eb.x,
                                (a1.y - st.x) * st.y * gb.y + eb.y,
                                (a1.z - st.x) * st.y * gb.z + eb.z,
                                (a1.w - st.x) * st.y * gb.w + eb.w);
    xs[512 + tid] = make_float4((b0.x - st.z) * st.w * ga.x + ea.x,
                                (b0.y - st.z) * st.w * ga.y + ea.y,
                                (b0.z - st.z) * st.w * ga.z + ea.z,
                                (b0.w - st.z) * st.w * ga.w + ea.w);
    xs[512 + tid + 256] = make_float4((b1.x - st.z) * st.w * gb.x + eb.x,
                                      (b1.y - st.z) * st.w * gb.y + eb.y,
                                      (b1.z - st.z) * st.w * gb.z + eb.z,
                                      (b1.w - st.z) * st.w * gb.w + eb.w);
    __syncthreads();
}

// ============================================================
// cp.async helpers
// ============================================================
__device__ __forceinline__ void cp16(uint32_t dst, const void* src) {
    asm volatile("cp.async.cg.shared.global [%0], [%1], 16;"
                 :: "r"(dst), "l"(src) : "memory");
}
__device__ __forceinline__ void cp_commit() {
    asm volatile("cp.async.commit_group;" ::: "memory");
}
__device__ __forceinline__ void cp_wait2() {
    asm volatile("cp.async.wait_group 2;" ::: "memory");
}

// ---- mbarrier + bulk-copy helpers ----
__device__ __forceinline__ void mbar_init(uint32_t a, uint32_t cnt) {
    asm volatile("mbarrier.init.shared.b64 [%0], %1;" :: "r"(a), "r"(cnt) : "memory");
}
__device__ __forceinline__ void mbar_expect_tx(uint32_t a, uint32_t tx) {
    asm volatile("mbarrier.arrive.expect_tx.shared.b64 _, [%0], %1;" :: "r"(a), "r"(tx) : "memory");
}
__device__ __forceinline__ void mbar_arrive(uint32_t a) {
    asm volatile("mbarrier.arrive.shared.b64 _, [%0];" :: "r"(a) : "memory");
}
__device__ __forceinline__ void mbar_wait(uint32_t a, uint32_t parity) {
    uint32_t done;
    asm volatile("{\n\t.reg .pred p;\n\t"
                 "mbarrier.try_wait.parity.acquire.cta.shared::cta.b64 p, [%1], %2;\n\t"
                 "selp.b32 %0, 1, 0, p;\n\t}"
                 : "=r"(done) : "r"(a), "r"(parity) : "memory");
    if (!done) {
        asm volatile("{\n\t.reg .pred P1;\n\t"
                     "W_%=:\n\t"
                     "mbarrier.try_wait.parity.acquire.cta.shared::cta.b64 P1, [%0], %1, 0x989680;\n\t"
                     "@P1 bra.uni D_%=;\n\t"
                     "bra.uni W_%=;\n\t"
                     "D_%=:\n\t}"
                     :: "r"(a), "r"(parity) : "memory");
    }
}
__device__ __forceinline__ void bulk_cp(uint32_t dst, const void* src, uint32_t bytes, uint32_t mbar) {
    asm volatile("cp.async.bulk.shared::cta.global.mbarrier::complete_tx::bytes [%0], [%1], %2, [%3];"
                 :: "r"(dst), "l"(src), "r"(bytes), "r"(mbar) : "memory");
}

// ============================================================
// dual-row cp.async-pipelined GEMV core (both batches).
// ============================================================
template <int NF4>
__device__ __forceinline__ float4 dual_dot_pipe(const float4* __restrict__ wA,
                                                const float4* __restrict__ wB,
                                                const float4* xs,
                                                float4* wslice, int lane) {
    constexpr int NSEG = NF4 / 32;
    uint32_t sb = (uint32_t)__cvta_generic_to_shared(wslice);
    #pragma unroll
    for (int p = 0; p < 2; p++) {
        cp16(sb + ((p * 64 + lane) << 4),      wA + p * 32 + lane);
        cp16(sb + ((p * 64 + 32 + lane) << 4), wB + p * 32 + lane);
        cp_commit();
    }
    float a00 = 0.f, a01 = 0.f, a10 = 0.f, a11 = 0.f;
    for (int s = 0; s < NSEG; s++) {
        int nx = s + 2;
        if (nx < NSEG) {
            int stn = nx % 3;
            cp16(sb + ((stn * 64 + lane) << 4),      wA + nx * 32 + lane);
            cp16(sb + ((stn * 64 + 32 + lane) << 4), wB + nx * 32 + lane);
        }
        cp_commit();
        cp_wait2();
        int st = s % 3;
        float4 wa = wslice[st * 64 + lane];
        float4 wb = wslice[st * 64 + 32 + lane];
        float4 xu = xs[s * 32 + lane];
        float4 xv = xs[NF4 + s * 32 + lane];
        a00 += wa.x*xu.x + wa.y*xu.y + wa.z*xu.z + wa.w*xu.w;
        a01 += wa.x*xv.x + wa.y*xv.y + wa.z*xv.z + wa.w*xv.w;
        a10 += wb.x*xu.x + wb.y*xu.y + wb.z*xu.z + wb.w*xu.w;
        a11 += wb.x*xv.x + wb.y*xv.y + wb.z*xv.z + wb.w*xv.w;
    }
    #pragma unroll
    for (int off = 16; off > 0; off >>= 1) {
        a00 += __shfl_down_sync(0xffffffffu, a00, off);
        a01 += __shfl_down_sync(0xffffffffu, a01, off);
        a10 += __shfl_down_sync(0xffffffffu, a10, off);
        a11 += __shfl_down_sync(0xffffffffu, a11, off);
    }
    return make_float4(a00, a01, a10, a11);
}

__device__ __forceinline__ void route_qkv(int j, float v0, float v1, int l) {
    int h = j / 384, c = j % 384;
    if (c < 128)      { g_q[0][h][c] = v0;             g_q[1][h][c] = v1; }
    else if (c < 256) { g_kscr[l][0][h][c-128] = v0;   g_kscr[l][1][h][c-128] = v1; }
    else              { g_vscr[l][0][h][c-256] = v0;   g_vscr[l][1][h][c-256] = v1; }
}

// ============================================================
// QKV projection (LN fused): 6144 rows = 384 chunks of 16, grid 384
// ============================================================
__global__ void __launch_bounds__(256, 4)
k_qkv(const float* __restrict__ qkv_w,
      const float* __restrict__ gam, const float* __restrict__ bet, int l) {
    __shared__ __align__(16) float4 xs[1024];
    __shared__ __align__(16) float4 wbuf[8 * 192];
    stage_ln(xs, gam, bet);
    int warp = threadIdx.x >> 5, lane = threadIdx.x & 31;
    int j = blockIdx.x * 16 + warp * 2;
    const float4* wA = (const float4*)(qkv_w + ((size_t)l * 3 * HIDN + j) * HIDN);
    const float4* wB = wA + 512;
    float4 r = dual_dot_pipe<512>(wA, wB, xs, wbuf + warp * 192, lane);
    if (lane == 0) {
        route_qkv(j,     r.x, r.y, l);
        route_qkv(j + 1, r.z, r.w, l);
    }
}

// ============================================================
// KV row addressing with scatter-write overrides
// ============================================================
__device__ __forceinline__ const float* kv_row(int l, int b, int h, int k,
        const float* __restrict__ heap, const float* __restrict__ off,
        const float (*scr)[BB][NHH][DDIM]) {
    if (l == 0) {
        if (k == SSEQ) return scr[0][b][h];
        return heap + (((size_t)(b * NHH + h)) * PHEAP + (size_t)k) * DDIM;
    }
    if (k < RRES) {
        if (k == 1023 && l >= 2) return scr[l - 2][b][h];
        return heap + (((size_t)(b * NHH + h)) * PHEAP + (size_t)(l - 1) * RRES + (size_t)k) * DDIM;
    }
    return off + (((((size_t)(l - 1)) * BB + b) * NHH + h) * OFFN + (size_t)(k - RRES)) * DDIM;
}

// ============================================================
// fused flash-decode partial + last-block combine
// grid (17, 32), block 256
// ============================================================
__global__ void k_flash(const float* __restrict__ kh, const float* __restrict__ ko,
                        const float* __restrict__ vh, const float* __restrict__ vo, int l) {
    int bh = blockIdx.y; int b = bh >> 4, h = bh & 15;
    int base = blockIdx.x * 128;
    int tid = threadIdx.x, warp = tid >> 5, lane = tid & 31;
    __shared__ float part[128][33];
    __shared__ float sc[128];
    __shared__ float red[128];
    __shared__ __align__(16) float4 vred[8][32];
    __shared__ __align__(16) float q_s[DDIM];
    __shared__ bool is_last;
    if (tid < DDIM) q_s[tid] = g_q[b][h][tid];
    __syncthreads();
    float4 q4 = ((const float4*)q_s)[lane];

    #pragma unroll 4
    for (int i = 0; i < 16; i++) {
        int r = warp * 16 + i, k = base + r;
        float p = 0.f;
        if (k < NK) {
            const float* kr = kv_row(l, b, h, k, kh, ko, g_kscr);
            float4 kk = ((const float4*)kr)[lane];
            p = q4.x*kk.x + q4.y*kk.y + q4.z*kk.z + q4.w*kk.w;
        }
        part[r][lane] = p;
    }
    __syncthreads();

    if (tid < 128) {
        float s = 0.f;
        #pragma unroll
        for (int i = 0; i < 32; i++) s += part[tid][i];
        s *= 0.088388347648318447f;
        if (base + tid >= NK) s = -1e30f;
        sc[tid] = s;
    }
    __syncthreads();
    if (tid < 64) red[tid] = fmaxf(sc[tid], sc[tid + 64]);
    __syncthreads();
    if (tid < 32) {
        float m = fmaxf(red[tid], red[tid + 32]);
        #pragma unroll
        for (int off = 16; off > 0; off >>= 1)
            m = fmaxf(m, __shfl_down_sync(0xffffffffu, m, off));
        if (tid == 0) red[0] = m;
    }
    __syncthreads();
    float mloc = red[0];
    __syncthreads();
    if (tid < 128) sc[tid] = expf(sc[tid] - mloc);
    __syncthreads();
    if (tid < 64) red[tid] = sc[tid] + sc[tid + 64];
    __syncthreads();
    if (tid < 32) {
        float s = red[tid] + red[tid + 32];
        #pragma unroll
        for (int off = 16; off > 0; off >>= 1)
            s += __shfl_down_sync(0xffffffffu, s, off);
        if (tid == 0) red[0] = s;
    }
    __syncthreads();
    float ssum = red[0];

    float4 acc = make_float4(0.f, 0.f, 0.f, 0.f);
    #pragma unroll 4
    for (int i = 0; i < 16; i++) {
        int r = warp * 16 + i, k = base + r;
        if (k < NK) {
            const float* vr = kv_row(l, b, h, k, vh, vo, g_vscr);
            float4 v4 = ((const float4*)vr)[lane];
            float pr = sc[r];
            acc.x += pr * v4.x; acc.y += pr * v4.y;
            acc.z += pr * v4.z; acc.w += pr * v4.w;
        }
    }
    vred[warp][lane] = acc;
    __syncthreads();
    if (tid < 128) {
        int li = tid >> 2, c = tid & 3;
        float o = 0.f;
        #pragma unroll
        for (int w2 = 0; w2 < 8; w2++) o += ((const float*)&vred[w2][li])[c];
        g_po[blockIdx.x][bh][tid] = o;
    }
    if (tid == 0) { g_pm[blockIdx.x][bh] = mloc; g_ps[blockIdx.x][bh] = ssum; }

    __threadfence();
    if (tid == 0) {
        unsigned int v = atomicAdd(&g_cnt[bh], 1u);
        is_last = (v == NCHUNK - 1);
    }
    __syncthreads();
    if (!is_last) return;
    __threadfence();
    if (tid == 0) g_cnt[bh] = 0;
    if (tid < 128) {
        float m = -1e30f;
        #pragma unroll
        for (int c = 0; c < NCHUNK; c++) m = fmaxf(m, g_pm[c][bh]);
        float S = 0.f, o = 0.f;
        #pragma unroll
        for (int c = 0; c < NCHUNK; c++) {
            float w = expf(g_pm[c][bh] - m);
            S += g_ps[c][bh] * w;
            o += g_po[c][bh][tid] * w;
        }
        g_x[b][h * DDIM + tid] += o / S;
    }
}

// ============================================================
// gelu
// ============================================================
__device__ __forceinline__ float gelu_exact(float x) {
    return 0.5f * x * (1.0f + erff(x * 0.70710678118654752f));
}

// ============================================================
// BULK-COPY GEMV (ffn1 / lmhead): block = 256 thr.
// chunk = 8 rows of HIDN floats (64KB contiguous) = 4 segments
// of 16KB (2 rows each). 4-slot ring (exactly one chunk in
// flight) streamed by cp.async.bulk + mbarrier; 8 warps consume
// each segment (4 warps/row, 128-f4 slices each).
// dynamic smem: xs 16KB + ring 64KB = 80KB -> 2 blocks/SM.
// mode 0: gelu -> g_h (device global).  mode 1: raw -> out0/out1.
// nchunks must be divisible by gridDim.x.
// ============================================================
__global__ void __launch_bounds__(256, 2)
k_gemv_bulk(const float* __restrict__ wbase,
            const float* __restrict__ gam, const float* __restrict__ bet,
            float* __restrict__ out0, float* __restrict__ out1,
            int nchunks, int mode) {
    extern __shared__ __align__(16) float4 dynb[];
    float4* xs   = dynb;            // 1024 f4
    float4* ring = dynb + 1024;     // 4 * 1024 f4 (4 slots x 16KB)
    __shared__ __align__(8) uint64_t mb_full[4];
    __shared__ __align__(8) uint64_t mb_empty[4];
    __shared__ float part[8][4][2];
    int tid = threadIdx.x, warp = tid >> 5, lane = tid & 31;
    uint32_t fullA  = (uint32_t)__cvta_generic_to_shared(mb_full);
    uint32_t emptyA = (uint32_t)__cvta_generic_to_shared(mb_empty);
    uint32_t ringA  = (uint32_t)__cvta_generic_to_shared(ring);

    if (tid == 0) {
        #pragma unroll
        for (int i = 0; i < 4; i++) { mbar_init(fullA + 8*i, 1); mbar_init(emptyA + 8*i, 8); }
    }
    __syncthreads();

    int G = gridDim.x;
    int nloc = nchunks / G;              // exact by construction
    int totalSegs = nloc * 4;

    // prologue: fill the ring with chunk 0's 4 segments (overlaps LN)
    if (tid == 0) {
        #pragma unroll
        for (int g = 0; g < 4; g++) {
            int rowbase = blockIdx.x * 8 + g * 2;     // chunk 0, seg g
            mbar_expect_tx(fullA + 8*g, 16384);
            bulk_cp(ringA + (uint32_t)g * 16384,
                    wbase + (size_t)rowbase * HIDN, 16384, fullA + 8*g);
        }
    }

    stage_ln(xs, gam, bet);

    int rowhalf = warp >> 2;         // 0..1 : which of the 2 rows in a segment
    int slice   = warp & 3;          // 0..3 : quarter of the row
    int fb = slice * 128;

    for (int g = 0; g < totalSegs; g++) {
        int slot = g & 3;
        mbar_wait(fullA + 8*slot, (g >> 2) & 1);
        const float4* wrow = ring + slot * 1024 + rowhalf * 512;
        float b0 = 0.f, b1 = 0.f;
        #pragma unroll
        for (int r = 0; r < 4; r++) {
            float4 wv = wrow[fb + r * 32 + lane];
            float4 u  = xs[fb + r * 32 + lane];
            float4 v  = xs[512 + fb + r * 32 + lane];
            b0 += wv.x*u.x + wv.y*u.y + wv.z*u.z + wv.w*u.w;
            b1 += wv.x*v.x + wv.y*v.y + wv.z*v.z + wv.w*v.w;
        }
        #pragma unroll
        for (int off = 16; off > 0; off >>= 1) {
            b0 += __shfl_down_sync(0xffffffffu, b0, off);
            b1 += __shfl_down_sync(0xffffffffu, b1, off);
        }
        int rowInChunk = (g & 3) * 2 + rowhalf;       // 0..7
        if (lane == 0) { part[rowInChunk][slice][0] = b0; part[rowInChunk][slice][1] = b1; }
        __syncwarp();
        if (lane == 0) mbar_arrive(emptyA + 8*slot);

        // producer refill (tid0) for segment g+4 (next chunk, same slot)
        if (tid == 0 && g + 4 < totalSegs) {
            int gn = g + 4;
            int u = gn >> 2;                          // chunk index
            mbar_wait(emptyA + 8*(gn & 3), (u - 1) & 1);
            int rowbase = (blockIdx.x + u * G) * 8 + (gn & 3) * 2;
            mbar_expect_tx(fullA + 8*(gn & 3), 16384);
            bulk_cp(ringA + (uint32_t)(gn & 3) * 16384,
                    wbase + (size_t)rowbase * HIDN, 16384, fullA + 8*(gn & 3));
        }

        if ((g & 3) == 3) {          // end of chunk: write the 8 rows
            __syncthreads();
            if (tid < 16) {
                int row = tid >> 1, bb = tid & 1;
                float s = part[row][0][bb] + part[row][1][bb]
                        + part[row][2][bb] + part[row][3][bb];
                int j = (blockIdx.x + (g >> 2) * G) * 8 + row;
                if (mode == 0) {
                    g_h[bb][j] = gelu_exact(s);       // device-global, resolved on device
                } else {
                    (bb ? out1 : out0)[j] = s;
                }
            }
            __syncthreads();
        }
    }
}

// ffn2: 2048 rows = 128 chunks of 16, grid 128; hs = 64KB dynamic smem
__global__ void __launch_bounds__(256, 2)
k_ffn2(const float* __restrict__ w, int l) {
    extern __shared__ float4 hs[];           // 4096 float4 = 64KB (both batches)
    __shared__ __align__(16) float4 wbuf[8 * 192];
    const float4* hsrc = (const float4*)g_h[0];
    for (int i = threadIdx.x; i < 4096; i += 256) hs[i] = hsrc[i];
    __syncthreads();
    int warp = threadIdx.x >> 5, lane = threadIdx.x & 31;
    int j = blockIdx.x * 16 + warp * 2;
    const float4* wA = (const float4*)(w + ((size_t)l * HIDN + j) * FFN);
    const float4* wB = wA + 2048;
    float4 r = dual_dot_pipe<2048>(wA, wB, hs, wbuf + warp * 192, lane);
    if (lane == 0) {
        g_x[0][j]     += r.x; g_x[1][j]     += r.y;
        g_x[0][j + 1] += r.z; g_x[1][j + 1] += r.w;
    }
}

__global__ void k_softmax(float* __restrict__ out) {
    int b = blockIdx.x;
    float* o = out + (size_t)b * VV;
    int tid = threadIdx.x;               // 1024
    __shared__ float red[1024];
    float m = -1e30f;
    for (int i = tid; i < VV; i += 1024) m = fmaxf(m, o[i]);
    red[tid] = m; __syncthreads();
    for (int off = 512; off > 0; off >>= 1) { if (tid < off) red[tid] = fmaxf(red[tid], red[tid + off]); __syncthreads(); }
    float mb = red[0];
    __syncthreads();
    float s = 0.f;
    for (int i = tid; i < VV; i += 1024) s += expf(o[i] - mb);
    red[tid] = s; __syncthreads();
    for (int off = 512; off > 0; off >>= 1) { if (tid < off) red[tid] += red[tid + off]; __syncthreads(); }
    float inv = 1.0f / red[0];
    __syncthreads();
    for (int i = tid; i < VV; i += 1024) o[i] = expf(o[i] - mb) * inv;
}

// ============================================================
// launch (graph-capturable: kernel launches only)
// ============================================================
#define BULK_DYN (81920)

extern "C" void kernel_launch(void* const* d_in, const int* in_sizes, int n_in,
                              void* d_out, int out_size) {
    const float* x      = (const float*)d_in[0];
    const float* qkv_w  = (const float*)d_in[1];
    const float* ffn1_w = (const float*)d_in[2];
    const float* ffn2_w = (const float*)d_in[3];
    const float* out_w  = (const float*)d_in[4];
    const float* ln_g   = (const float*)d_in[5];
    const float* ln_b   = (const float*)d_in[6];
    const float* k_heap = (const float*)d_in[7];
    const float* v_heap = (const float*)d_in[8];
    const float* k_off  = (const float*)d_in[9];
    const float* v_off  = (const float*)d_in[10];
    const int*   pos    = (const int*)  d_in[11];
    float* out = (float*)d_out;

    cudaFuncSetAttribute(k_ffn2, cudaFuncAttributeMaxDynamicSharedMemorySize, 65536);
    cudaFuncSetAttribute(k_gemv_bulk, cudaFuncAttributeMaxDynamicSharedMemorySize, BULK_DYN);

    k_init<<<BB, 256>>>(x, pos);

    for (int l = 0; l < LLN; l++) {
        k_qkv<<<384, 256>>>(qkv_w, ln_g, ln_b, l);
        { dim3 gs(NCHUNK, BB * NHH); k_flash<<<gs, 256>>>(k_heap, k_off, v_heap, v_off, l); }
        // ffn1: 8192 rows = 1024 chunks of 8, grid 256 (4 chunks/block), bulk path
        k_gemv_bulk<<<256, 256, BULK_DYN>>>(ffn1_w + (size_t)l * FFN * HIDN,
                                            ln_g, ln_b, nullptr, nullptr, 1024, 0);
        k_ffn2<<<128, 256, 65536>>>(ffn2_w, l);
    }

    // lmhead: 32000 rows = 4000 chunks of 8, grid 250 (16 chunks/block), bulk path
    k_gemv_bulk<<<250, 256, BULK_DYN>>>(out_w, ln_g, ln_b, out, out + VV, 4000, 1);
    k_softmax<<<BB, 1024>>>(out);
}

// round 15
// speedup vs baseline: 1.0320x; 1.0320x over previous
#include <cuda_runtime.h>
#include <math.h>
#include <stdint.h>

// ---- problem constants ----
#define BB    2
#define HIDN  2048
#define NHH   16
#define LLN   8
#define VV    32000
#define DDIM  128
#define OFFN  1024
#define RRES  1025
#define PHEAP 11272
#define NK    2049
#define FFN   8192
#define SSEQ  2048
#define NCHUNK 17

// ---- device scratch (allocation-free) ----
__device__ __align__(16) float g_x [BB][HIDN];
__device__ __align__(16) float g_q [BB][NHH][DDIM];
__device__ __align__(16) float g_kscr[LLN][BB][NHH][DDIM];
__device__ __align__(16) float g_vscr[LLN][BB][NHH][DDIM];
__device__ __align__(16) float g_h[BB][FFN];
__device__ float g_pm[NCHUNK][BB * NHH];
__device__ float g_ps[NCHUNK][BB * NHH];
__device__ __align__(16) float g_po[NCHUNK][BB * NHH][DDIM];
__device__ unsigned int g_cnt[BB * NHH];   // zero-init; self-resetting

// ============================================================
// x = x + sinusoidal PE(pos)
// ============================================================
__global__ void k_init(const float* __restrict__ x, const int* __restrict__ posp) {
    int b = blockIdx.x;
    float pos = (float)(*posp);
    for (int e = threadIdx.x; e < HIDN; e += blockDim.x) {
        int i = e >> 1;
        float div = expf(-logf(10000.0f) * (2.0f * (float)i) / (float)HIDN);
        float ang = pos * div;
        float pe = (e & 1) ? cosf(ang) : sinf(ang);
        g_x[b][e] = x[(size_t)b * HIDN + e] + pe;
    }
}

// ============================================================
// LN prologue (warp-shuffle, 3 barriers). block = 256 threads.
// xs layout: [0,512) = batch0 float4, [512,1024) = batch1 float4.
// ============================================================
__device__ __forceinline__ void stage_ln(float4* xs,
                                         const float* __restrict__ gam,
                                         const float* __restrict__ bet) {
    int tid = threadIdx.x, lane = tid & 31, warp = tid >> 5;
    __shared__ float4 wred[8];
    __shared__ float4 stats;   // mean0, rstd0, mean1, rstd1
    const float4* x0 = (const float4*)g_x[0];
    const float4* x1 = (const float4*)g_x[1];
    float4 a0 = x0[tid], a1 = x0[tid + 256];
    float4 b0 = x1[tid], b1 = x1[tid + 256];
    float s0 = a0.x + a0.y + a0.z + a0.w + a1.x + a1.y + a1.z + a1.w;
    float s1 = b0.x + b0.y + b0.z + b0.w + b1.x + b1.y + b1.z + b1.w;
    float q0 = a0.x*a0.x + a0.y*a0.y + a0.z*a0.z + a0.w*a0.w
             + a1.x*a1.x + a1.y*a1.y + a1.z*a1.z + a1.w*a1.w;
    float q1 = b0.x*b0.x + b0.y*b0.y + b0.z*b0.z + b0.w*b0.w
             + b1.x*b1.x + b1.y*b1.y + b1.z*b1.z + b1.w*b1.w;
    #pragma unroll
    for (int off = 16; off > 0; off >>= 1) {
        s0 += __shfl_down_sync(0xffffffffu, s0, off);
        q0 += __shfl_down_sync(0xffffffffu, q0, off);
        s1 += __shfl_down_sync(0xffffffffu, s1, off);
        q1 += __shfl_down_sync(0xffffffffu, q1, off);
    }
    if (lane == 0) wred[warp] = make_float4(s0, q0, s1, q1);
    __syncthreads();
    if (warp == 0) {
        float4 v = wred[lane & 7];
        float t0 = v.x, t1 = v.y, t2 = v.z, t3 = v.w;
        #pragma unroll
        for (int off = 4; off > 0; off >>= 1) {
            t0 += __shfl_down_sync(0xffffffffu, t0, off, 8);
            t1 += __shfl_down_sync(0xffffffffu, t1, off, 8);
            t2 += __shfl_down_sync(0xffffffffu, t2, off, 8);
            t3 += __shfl_down_sync(0xffffffffu, t3, off, 8);
        }
        if (lane == 0) {
            float mean0 = t0 * (1.0f / HIDN);
            float mean1 = t2 * (1.0f / HIDN);
            float var0  = t1 * (1.0f / HIDN) - mean0 * mean0;
            float var1  = t3 * (1.0f / HIDN) - mean1 * mean1;
            stats = make_float4(mean0, rsqrtf(var0 + 1e-5f),
                                mean1, rsqrtf(var1 + 1e-5f));
        }
    }
    __syncthreads();
    float4 st = stats;
    const float4* g4 = (const float4*)gam;
    const float4* e4 = (const float4*)bet;
    float4 ga = g4[tid], gb = g4[tid + 256];
    float4 ea = e4[tid], eb = e4[tid + 256];
    xs[tid] = make_float4((a0.x - st.x) * st.y * ga.x + ea.x,
                          (a0.y - st.x) * st.y * ga.y + ea.y,
                          (a0.z - st.x) * st.y * ga.z + ea.z,
                          (a0.w - st.x) * st.y * ga.w + ea.w);
    xs[tid + 256] = make_float4((a1.x - st.x) * st.y * gb.x + eb.x,
                                (a1.y - st.x) * st.y * gb.y + eb.y,
                                (a1.z - st.x) * st.y * gb.z + eb.z,
                                (a1.w - st.x) * st.y * gb.w + eb.w);
    xs[512 + tid] = make_float4((b0.x - st.z) * st.w * ga.x + ea.x,
                                (b0.y - st.z) * st.w * ga.y + ea.y,
                                (b0.z - st.z) * st.w * ga.z + ea.z,
                                (b0.w - st.z) * st.w * ga.w + ea.w);
    xs[512 + tid + 256] = make_float4((b1.x - st.z) * st.w * gb.x + eb.x,
                                      (b1.y - st.z) * st.w * gb.y + eb.y,
                                      (b1.z - st.z) * st.w * gb.z + eb.z,
                                      (b1.w - st.z) * st.w * gb.w + eb.w);
    __syncthreads();
}

// ============================================================
// cp.async helpers
// ============================================================
__device__ __forceinline__ void cp16(uint32_t dst, const void* src) {
    asm volatile("cp.async.cg.shared.global [%0], [%1], 16;"
                 :: "r"(dst), "l"(src) : "memory");
}
__device__ __forceinline__ void cp_commit() {
    asm volatile("cp.async.commit_group;" ::: "memory");
}
__device__ __forceinline__ void cp_wait2() {
    asm volatile("cp.async.wait_group 2;" ::: "memory");
}

// ============================================================
// dual-row cp.async-pipelined GEMV core (both batches).
// wslice: 3 stages x 2 rows x 32 float4 = 192 float4 per warp
// ============================================================
template <int NF4>
__device__ __forceinline__ float4 dual_dot_pipe(const float4* __restrict__ wA,
                                                const float4* __restrict__ wB,
                                                const float4* xs,
                                                float4* wslice, int lane) {
    constexpr int NSEG = NF4 / 32;
    uint32_t sb = (uint32_t)__cvta_generic_to_shared(wslice);
    #pragma unroll
    for (int p = 0; p < 2; p++) {
        cp16(sb + ((p * 64 + lane) << 4),      wA + p * 32 + lane);
        cp16(sb + ((p * 64 + 32 + lane) << 4), wB + p * 32 + lane);
        cp_commit();
    }
    float a00 = 0.f, a01 = 0.f, a10 = 0.f, a11 = 0.f;
    for (int s = 0; s < NSEG; s++) {
        int nx = s + 2;
        if (nx < NSEG) {
            int stn = nx % 3;
            cp16(sb + ((stn * 64 + lane) << 4),      wA + nx * 32 + lane);
            cp16(sb + ((stn * 64 + 32 + lane) << 4), wB + nx * 32 + lane);
        }
        cp_commit();
        cp_wait2();
        int st = s % 3;
        float4 wa = wslice[st * 64 + lane];
        float4 wb = wslice[st * 64 + 32 + lane];
        float4 xu = xs[s * 32 + lane];
        float4 xv = xs[NF4 + s * 32 + lane];
        a00 += wa.x*xu.x + wa.y*xu.y + wa.z*xu.z + wa.w*xu.w;
        a01 += wa.x*xv.x + wa.y*xv.y + wa.z*xv.z + wa.w*xv.w;
        a10 += wb.x*xu.x + wb.y*xu.y + wb.z*xu.z + wb.w*xu.w;
        a11 += wb.x*xv.x + wb.y*xv.y + wb.z*xv.z + wb.w*xv.w;
    }
    #pragma unroll
    for (int off = 16; off > 0; off >>= 1) {
        a00 += __shfl_down_sync(0xffffffffu, a00, off);
        a01 += __shfl_down_sync(0xffffffffu, a01, off);
        a10 += __shfl_down_sync(0xffffffffu, a10, off);
        a11 += __shfl_down_sync(0xffffffffu, a11, off);
    }
    return make_float4(a00, a01, a10, a11);
}

// single-row pipe (ffn2): 3 stages x 32 float4 = 96 f4 per warp
template <int NF4>
__device__ __forceinline__ float2 sdot_pipe(const float4* __restrict__ w,
                                            const float4* xs,
                                            float4* ws, int lane) {
    constexpr int NSEG = NF4 / 32;
    uint32_t sb = (uint32_t)__cvta_generic_to_shared(ws);
    cp16(sb + (lane << 4),        w + lane);        cp_commit();
    cp16(sb + ((32 + lane) << 4), w + 32 + lane);   cp_commit();
    float a0 = 0.f, a1 = 0.f;
    for (int s = 0; s < NSEG; s++) {
        int nx = s + 2;
        if (nx < NSEG) {
            int stn = nx % 3;
            cp16(sb + ((stn * 32 + lane) << 4), w + nx * 32 + lane);
        }
        cp_commit();
        cp_wait2();
        int st = s % 3;
        float4 wv = ws[st * 32 + lane];
        float4 xu = xs[s * 32 + lane];
        float4 xv = xs[NF4 + s * 32 + lane];
        a0 += wv.x*xu.x + wv.y*xu.y + wv.z*xu.z + wv.w*xu.w;
        a1 += wv.x*xv.x + wv.y*xv.y + wv.z*xv.z + wv.w*xv.w;
    }
    #pragma unroll
    for (int off = 16; off > 0; off >>= 1) {
        a0 += __shfl_down_sync(0xffffffffu, a0, off);
        a1 += __shfl_down_sync(0xffffffffu, a1, off);
    }
    return make_float2(a0, a1);
}

__device__ __forceinline__ void route_qkv(int j, float v0, float v1, int l) {
    int h = j / 384, c = j % 384;
    if (c < 128)      { g_q[0][h][c] = v0;             g_q[1][h][c] = v1; }
    else if (c < 256) { g_kscr[l][0][h][c-128] = v0;   g_kscr[l][1][h][c-128] = v1; }
    else              { g_vscr[l][0][h][c-256] = v0;   g_vscr[l][1][h][c-256] = v1; }
}

// ============================================================
// QKV projection (LN fused): 6144 rows = 384 blocks x 16
// ============================================================
__global__ void __launch_bounds__(256, 4)
k_qkv(const float* __restrict__ qkv_w,
      const float* __restrict__ gam, const float* __restrict__ bet, int l) {
    __shared__ __align__(16) float4 xs[1024];
    __shared__ __align__(16) float4 wbuf[8 * 192];
    stage_ln(xs, gam, bet);
    int warp = threadIdx.x >> 5, lane = threadIdx.x & 31;
    int j = blockIdx.x * 16 + warp * 2;
    const float4* wA = (const float4*)(qkv_w + ((size_t)l * 3 * HIDN + j) * HIDN);
    const float4* wB = wA + 512;
    float4 r = dual_dot_pipe<512>(wA, wB, xs, wbuf + warp * 192, lane);
    if (lane == 0) {
        route_qkv(j,     r.x, r.y, l);
        route_qkv(j + 1, r.z, r.w, l);
    }
}

// ============================================================
// KV row addressing with scatter-write overrides
// ============================================================
__device__ __forceinline__ const float* kv_row(int l, int b, int h, int k,
        const float* __restrict__ heap, const float* __restrict__ off,
        const float (*scr)[BB][NHH][DDIM]) {
    if (l == 0) {
        if (k == SSEQ) return scr[0][b][h];
        return heap + (((size_t)(b * NHH + h)) * PHEAP + (size_t)k) * DDIM;
    }
    if (k < RRES) {
        if (k == 1023 && l >= 2) return scr[l - 2][b][h];
        return heap + (((size_t)(b * NHH + h)) * PHEAP + (size_t)(l - 1) * RRES + (size_t)k) * DDIM;
    }
    return off + (((((size_t)(l - 1)) * BB + b) * NHH + h) * OFFN + (size_t)(k - RRES)) * DDIM;
}

// ============================================================
// fused flash-decode partial + last-block combine
// grid (17, 32), block 256
// ============================================================
__global__ void k_flash(const float* __restrict__ kh, const float* __restrict__ ko,
                        const float* __restrict__ vh, const float* __restrict__ vo, int l) {
    int bh = blockIdx.y; int b = bh >> 4, h = bh & 15;
    int base = blockIdx.x * 128;
    int tid = threadIdx.x, warp = tid >> 5, lane = tid & 31;
    __shared__ float part[128][33];
    __shared__ float sc[128];
    __shared__ float red[128];
    __shared__ __align__(16) float4 vred[8][32];
    __shared__ __align__(16) float q_s[DDIM];
    __shared__ bool is_last;
    if (tid < DDIM) q_s[tid] = g_q[b][h][tid];
    __syncthreads();
    float4 q4 = ((const float4*)q_s)[lane];

    #pragma unroll 4
    for (int i = 0; i < 16; i++) {
        int r = warp * 16 + i, k = base + r;
        float p = 0.f;
        if (k < NK) {
            const float* kr = kv_row(l, b, h, k, kh, ko, g_kscr);
            float4 kk = ((const float4*)kr)[lane];
            p = q4.x*kk.x + q4.y*kk.y + q4.z*kk.z + q4.w*kk.w;
        }
        part[r][lane] = p;
    }
    __syncthreads();

    if (tid < 128) {
        float s = 0.f;
        #pragma unroll
        for (int i = 0; i < 32; i++) s += part[tid][i];
        s *= 0.088388347648318447f;
        if (base + tid >= NK) s = -1e30f;
        sc[tid] = s;
    }
    __syncthreads();
    if (tid < 64) red[tid] = fmaxf(sc[tid], sc[tid + 64]);
    __syncthreads();
    if (tid < 32) {
        float m = fmaxf(red[tid], red[tid + 32]);
        #pragma unroll
        for (int off = 16; off > 0; off >>= 1)
            m = fmaxf(m, __shfl_down_sync(0xffffffffu, m, off));
        if (tid == 0) red[0] = m;
    }
    __syncthreads();
    float mloc = red[0];
    __syncthreads();
    if (tid < 128) sc[tid] = expf(sc[tid] - mloc);
    __syncthreads();
    if (tid < 64) red[tid] = sc[tid] + sc[tid + 64];
    __syncthreads();
    if (tid < 32) {
        float s = red[tid] + red[tid + 32];
        #pragma unroll
        for (int off = 16; off > 0; off >>= 1)
            s += __shfl_down_sync(0xffffffffu, s, off);
        if (tid == 0) red[0] = s;
    }
    __syncthreads();
    float ssum = red[0];

    float4 acc = make_float4(0.f, 0.f, 0.f, 0.f);
    #pragma unroll 4
    for (int i = 0; i < 16; i++) {
        int r = warp * 16 + i, k = base + r;
        if (k < NK) {
            const float* vr = kv_row(l, b, h, k, vh, vo, g_vscr);
            float4 v4 = ((const float4*)vr)[lane];
            float pr = sc[r];
            acc.x += pr * v4.x; acc.y += pr * v4.y;
            acc.z += pr * v4.z; acc.w += pr * v4.w;
        }
    }
    vred[warp][lane] = acc;
    __syncthreads();
    if (tid < 128) {
        int li = tid >> 2, c = tid & 3;
        float o = 0.f;
        #pragma unroll
        for (int w2 = 0; w2 < 8; w2++) o += ((const float*)&vred[w2][li])[c];
        g_po[blockIdx.x][bh][tid] = o;
    }
    if (tid == 0) { g_pm[blockIdx.x][bh] = mloc; g_ps[blockIdx.x][bh] = ssum; }

    __threadfence();
    if (tid == 0) {
        unsigned int v = atomicAdd(&g_cnt[bh], 1u);
        is_last = (v == NCHUNK - 1);
    }
    __syncthreads();
    if (!is_last) return;
    __threadfence();
    if (tid == 0) g_cnt[bh] = 0;
    if (tid < 128) {
        float m = -1e30f;
        #pragma unroll
        for (int c = 0; c < NCHUNK; c++) m = fmaxf(m, g_pm[c][bh]);
        float S = 0.f, o = 0.f;
        #pragma unroll
        for (int c = 0; c < NCHUNK; c++) {
            float w = expf(g_pm[c][bh] - m);
            S += g_ps[c][bh] * w;
            o += g_po[c][bh][tid] * w;
        }
        g_x[b][h * DDIM + tid] += o / S;
    }
}

// ============================================================
// FFN
// ============================================================
__device__ __forceinline__ float gelu_exact(float x) {
    return 0.5f * x * (1.0f + erff(x * 0.70710678118654752f));
}

// ffn1: 8192 rows = 512 blocks x 16
__global__ void __launch_bounds__(256, 4)
k_ffn1(const float* __restrict__ w,
       const float* __restrict__ gam, const float* __restrict__ bet, int l) {
    __shared__ __align__(16) float4 xs[1024];
    __shared__ __align__(16) float4 wbuf[8 * 192];
    stage_ln(xs, gam, bet);
    int warp = threadIdx.x >> 5, lane = threadIdx.x & 31;
    int j = blockIdx.x * 16 + warp * 2;
    const float4* wA = (const float4*)(w + ((size_t)l * FFN + j) * HIDN);
    const float4* wB = wA + 512;
    float4 r = dual_dot_pipe<512>(wA, wB, xs, wbuf + warp * 192, lane);
    if (lane == 0) {
        g_h[0][j]     = gelu_exact(r.x); g_h[1][j]     = gelu_exact(r.y);
        g_h[0][j + 1] = gelu_exact(r.z); g_h[1][j + 1] = gelu_exact(r.w);
    }
}

// ffn2: 2048 rows = 256 blocks x 8, one row per warp (all SMs covered).
// hs = 64KB dynamic (both batches); wbuf 12KB static. 2 blocks/SM.
__global__ void __launch_bounds__(256, 2)
k_ffn2(const float* __restrict__ w, int l) {
    extern __shared__ float4 hs[];           // 4096 float4 = 64KB
    __shared__ __align__(16) float4 wbuf[8 * 96];
    int tid = threadIdx.x, warp = tid >> 5, lane = tid & 31;
    const float4* hsrc = (const float4*)g_h[0];
    for (int i = tid; i < 4096; i += 256) hs[i] = hsrc[i];
    __syncthreads();
    int j = blockIdx.x * 8 + warp;
    const float4* wr = (const float4*)(w + ((size_t)l * HIDN + j) * FFN);
    float2 r = sdot_pipe<2048>(wr, hs, wbuf + warp * 96, lane);
    if (lane == 0) { g_x[0][j] += r.x; g_x[1][j] += r.y; }
}

// ============================================================
// LM head (LN fused): 32000 rows = 2000 chunks of 16, grid 500 x 4 chunks
// ============================================================
__global__ void __launch_bounds__(256, 4)
k_lmhead(const float* __restrict__ w,
         const float* __restrict__ gam, const float* __restrict__ bet,
         float* __restrict__ out) {
    __shared__ __align__(16) float4 xs[1024];
    __shared__ __align__(16) float4 wbuf[8 * 192];
    stage_ln(xs, gam, bet);
    int warp = threadIdx.x >> 5, lane = threadIdx.x & 31;
    for (int c = blockIdx.x; c < 2000; c += 500) {
        int j = c * 16 + warp * 2;
        const float4* wA = (const float4*)(w + (size_t)j * HIDN);
        const float4* wB = wA + 512;
        float4 r = dual_dot_pipe<512>(wA, wB, xs, wbuf + warp * 192, lane);
        if (lane == 0) {
            out[j]     = r.x; out[(size_t)VV + j]     = r.y;
            out[j + 1] = r.z; out[(size_t)VV + j + 1] = r.w;
        }
    }
}

__global__ void k_softmax(float* __restrict__ out) {
    int b = blockIdx.x;
    float* o = out + (size_t)b * VV;
    int tid = threadIdx.x;               // 1024
    __shared__ float red[1024];
    float m = -1e30f;
    for (int i = tid; i < VV; i += 1024) m = fmaxf(m, o[i]);
    red[tid] = m; __syncthreads();
    for (int off = 512; off > 0; off >>= 1) { if (tid < off) red[tid] = fmaxf(red[tid], red[tid + off]); __syncthreads(); }
    float mb = red[0];
    __syncthreads();
    float s = 0.f;
    for (int i = tid; i < VV; i += 1024) s += expf(o[i] - mb);
    red[tid] = s; __syncthreads();
    for (int off = 512; off > 0; off >>= 1) { if (tid < off) red[tid] += red[tid + off]; __syncthreads(); }
    float inv = 1.0f / red[0];
    __syncthreads();
    for (int i = tid; i < VV; i += 1024) o[i] = expf(o[i] - mb) * inv;
}

// ============================================================
// launch (graph-capturable: kernel launches only)
// ============================================================
extern "C" void kernel_launch(void* const* d_in, const int* in_sizes, int n_in,
                              void* d_out, int out_size) {
    const float* x      = (const float*)d_in[0];
    const float* qkv_w  = (const float*)d_in[1];
    const float* ffn1_w = (const float*)d_in[2];
    const float* ffn2_w = (const float*)d_in[3];
    const float* out_w  = (const float*)d_in[4];
    const float* ln_g   = (const float*)d_in[5];
    const float* ln_b   = (const float*)d_in[6];
    const float* k_heap = (const float*)d_in[7];
    const float* v_heap = (const float*)d_in[8];
    const float* k_off  = (const float*)d_in[9];
    const float* v_off  = (const float*)d_in[10];
    const int*   pos    = (const int*)  d_in[11];
    float* out = (float*)d_out;

    cudaFuncSetAttribute(k_ffn2, cudaFuncAttributeMaxDynamicSharedMemorySize, 65536);

    k_init<<<BB, 256>>>(x, pos);

    for (int l = 0; l < LLN; l++) {
        k_qkv<<<384, 256>>>(qkv_w, ln_g, ln_b, l);
        { dim3 gs(NCHUNK, BB * NHH); k_flash<<<gs, 256>>>(k_heap, k_off, v_heap, v_off, l); }
        k_ffn1<<<512, 256>>>(ffn1_w, ln_g, ln_b, l);
        k_ffn2<<<256, 256, 65536>>>(ffn2_w, l);
    }

    k_lmhead<<<500, 256>>>(out_w, ln_g, ln_b, out);
    k_softmax<<<BB, 1024>>>(out);
}